// round 1
// baseline (speedup 1.0000x reference)
#include <cuda_runtime.h>
#include <math.h>

#define BB 2048
#define TT 80
#define LL 128
#define NCTA 148

// Scratch (no device mallocs allowed)
__device__ float g_E[LL * LL];   // exp(trans)
__device__ float g_num[BB];      // gold-path numerator per batch row

// -------------------------------------------------------------------------
// prep: blocks [0,8) compute numerators (1 thread per batch row),
//       blocks [8,72) compute E = exp(trans)
// -------------------------------------------------------------------------
__global__ void prep_kernel(const float* __restrict__ x,
                            const float* __restrict__ trans,
                            const float* __restrict__ st,
                            const float* __restrict__ et,
                            const int*   __restrict__ y)
{
    int idx = blockIdx.x * 256 + threadIdx.x;
    if (blockIdx.x < 8) {
        int b = idx;                      // 0..2047
        const int*   yb = y + b * TT;
        const float* xb = x + (size_t)b * TT * LL;
        int prev = yb[0];
        float num = st[prev] + xb[prev];
        #pragma unroll 4
        for (int t = 1; t < TT; t++) {
            int cur = yb[t];
            num += xb[t * LL + cur] + trans[prev * LL + cur];
            prev = cur;
        }
        num += et[prev];
        g_num[b] = num;
    } else {
        int e = idx - 2048;               // 0..16383 over 64 blocks
        if (e < LL * LL) g_E[e] = __expf(trans[e]);
    }
}

// -------------------------------------------------------------------------
// Forward algorithm, linear domain, persistent CTAs.
// 148 CTAs x 256 threads. Each CTA owns rows [cta*B/148, (cta+1)*B/148):
// 13 or 14 rows, split into two halves of <=7 rows (threads 0-127 / 128-255).
// Thread (half, j) holds accumulator column j for its half's 7 (padded) rows.
// E resident in SMEM; v (linear alpha) in SMEM; x streamed from GMEM.
// Renormalize by row max every 4 steps; per-thread log-scale s[r].
// -------------------------------------------------------------------------
extern __shared__ float smem[];

__global__ void __launch_bounds__(256, 1) crf_fwd_kernel(
    const float* __restrict__ x,
    const float* __restrict__ st,
    const float* __restrict__ et,
    float*       __restrict__ out)
{
    float* sE   = smem;                   // 16384 floats
    float* sV   = smem + LL * LL;         // 14 * 128 floats
    float* sRed = sV + 14 * LL;           // 2 * 7 * 4 floats

    const int tid  = threadIdx.x;
    const int j    = tid & 127;
    const int half = tid >> 7;
    const int warp = tid >> 5;
    const int win  = warp & 3;            // warp index within half

    const int cta   = blockIdx.x;
    const int row0  = (cta * BB) / NCTA;
    const int row1  = ((cta + 1) * BB) / NCTA;
    const int nrows = row1 - row0;
    const int nh0   = (nrows + 1) >> 1;
    const int my0   = half ? nh0 : 0;
    const int myn   = half ? (nrows - nh0) : nh0;   // <= 7

    // Stage E into shared (coalesced, conflict-free reads later: sE[i*128+j])
    for (int k = tid; k < LL * LL; k += 256) sE[k] = g_E[k];

    const float e_end = __expf(et[j]);
    const float stj   = st[j];

    // Row indices (pad to 7 per half, clamp addresses; padded results discarded)
    int grow[7];
    #pragma unroll
    for (int r = 0; r < 7; r++) {
        int g = row0 + my0 + r;
        grow[r] = (g < BB) ? g : (BB - 1);
    }

    // t = 0 init: v0 = exp(start + x[:,0])
    #pragma unroll
    for (int r = 0; r < 7; r++) {
        float v0 = __expf(stj + x[(size_t)grow[r] * (TT * LL) + j]);
        sV[(my0 + r) * LL + j] = v0;
    }
    float s[7];
    #pragma unroll
    for (int r = 0; r < 7; r++) s[r] = 0.0f;
    __syncthreads();

    for (int t = 1; t < TT; t++) {
        // Prefetch emissions for this step (coalesced 512B per row)
        float xr[7];
        #pragma unroll
        for (int r = 0; r < 7; r++)
            xr[r] = x[(size_t)grow[r] * (TT * LL) + t * LL + j];

        float acc[7];
        #pragma unroll
        for (int r = 0; r < 7; r++) acc[r] = 0.0f;

        const float4* v4 = (const float4*)(sV + my0 * LL);
        #pragma unroll 8
        for (int ib = 0; ib < 32; ib++) {
            const int i = ib * 4;
            float e0 = sE[(i + 0) * LL + j];
            float e1 = sE[(i + 1) * LL + j];
            float e2 = sE[(i + 2) * LL + j];
            float e3 = sE[(i + 3) * LL + j];
            #pragma unroll
            for (int r = 0; r < 7; r++) {
                float4 vv = v4[r * (LL / 4) + ib];   // broadcast, 1 phase
                acc[r] = fmaf(vv.x, e0, acc[r]);
                acc[r] = fmaf(vv.y, e1, acc[r]);
                acc[r] = fmaf(vv.z, e2, acc[r]);
                acc[r] = fmaf(vv.w, e3, acc[r]);
            }
        }

        float val[7];
        #pragma unroll
        for (int r = 0; r < 7; r++) val[r] = acc[r] * __expf(xr[r]);

        __syncthreads();   // all readers of old sV done before overwrite

        if ((t & 3) == 0) {
            // Row-max over the 128 threads of this half
            #pragma unroll
            for (int r = 0; r < 7; r++) {
                float m = val[r];
                #pragma unroll
                for (int o = 16; o > 0; o >>= 1)
                    m = fmaxf(m, __shfl_xor_sync(0xffffffffu, m, o));
                if ((tid & 31) == 0) sRed[(half * 7 + r) * 4 + win] = m;
            }
            __syncthreads();
            #pragma unroll
            for (int r = 0; r < 7; r++) {
                const float* p = &sRed[(half * 7 + r) * 4];
                float m = fmaxf(fmaxf(p[0], p[1]), fmaxf(p[2], p[3]));
                val[r] *= (1.0f / m);
                s[r] += logf(m);
            }
        }

        #pragma unroll
        for (int r = 0; r < 7; r++)
            sV[(my0 + r) * LL + j] = val[r];
        __syncthreads();
    }

    // Epilogue: Z = sum_j v[j] * exp(end[j]); out = num - (s + log Z)
    #pragma unroll
    for (int r = 0; r < 7; r++) {
        float z = sV[(my0 + r) * LL + j] * e_end;
        #pragma unroll
        for (int o = 16; o > 0; o >>= 1)
            z += __shfl_xor_sync(0xffffffffu, z, o);
        if ((tid & 31) == 0) sRed[(half * 7 + r) * 4 + win] = z;
    }
    __syncthreads();
    if (j == 0) {
        #pragma unroll
        for (int r = 0; r < 7; r++) {
            if (r < myn) {
                const float* p = &sRed[(half * 7 + r) * 4];
                float Z = (p[0] + p[1]) + (p[2] + p[3]);
                int g = row0 + my0 + r;
                out[g] = g_num[g] - (s[r] + logf(Z));
            }
        }
    }
}

// -------------------------------------------------------------------------
extern "C" void kernel_launch(void* const* d_in, const int* in_sizes, int n_in,
                              void* d_out, int out_size)
{
    const float* x     = (const float*)d_in[0];
    const float* trans = (const float*)d_in[1];
    const float* st    = (const float*)d_in[2];
    const float* et    = (const float*)d_in[3];
    const int*   y     = (const int*)  d_in[4];
    float*       out   = (float*)d_out;

    const size_t smem_bytes = (size_t)(LL * LL + 14 * LL + 2 * 7 * 4) * sizeof(float);
    cudaFuncSetAttribute(crf_fwd_kernel,
                         cudaFuncAttributeMaxDynamicSharedMemorySize,
                         (int)smem_bytes);

    prep_kernel<<<72, 256>>>(x, trans, st, et, y);
    crf_fwd_kernel<<<NCTA, 256, smem_bytes>>>(x, st, et, out);
}

// round 2
// speedup vs baseline: 1.0240x; 1.0240x over previous
#include <cuda_runtime.h>
#include <math.h>

#define BB 2048
#define TT 80
#define LL 128
#define NCTA 148

typedef unsigned long long u64;

__device__ float g_E[LL * LL];   // exp(trans)
__device__ float g_num[BB];      // gold-path numerator per batch row

// ---- packed f32x2 helpers (FFMA2 is PTX-only; ptxas never auto-fuses) ----
__device__ __forceinline__ u64 ffma2(u64 a, u64 b, u64 c) {
    u64 d;
    asm("fma.rn.f32x2 %0, %1, %2, %3;" : "=l"(d) : "l"(a), "l"(b), "l"(c));
    return d;
}
__device__ __forceinline__ u64 fadd2(u64 a, u64 b) {
    u64 d;
    asm("add.rn.f32x2 %0, %1, %2;" : "=l"(d) : "l"(a), "l"(b));
    return d;
}
__device__ __forceinline__ u64 pack2(float lo, float hi) {
    u64 d;
    asm("mov.b64 %0, {%1, %2};" : "=l"(d)
        : "r"(__float_as_uint(lo)), "r"(__float_as_uint(hi)));
    return d;
}
__device__ __forceinline__ void unpack2(u64 v, float& lo, float& hi) {
    unsigned a, b;
    asm("mov.b64 {%0, %1}, %2;" : "=r"(a), "=r"(b) : "l"(v));
    lo = __uint_as_float(a);
    hi = __uint_as_float(b);
}

// -------------------------------------------------------------------------
// prep: blocks [0,256): numerators, one warp per batch row (parallel over t,
//       shuffle-reduce). blocks [256,320): E = exp(trans).
// -------------------------------------------------------------------------
__global__ void prep_kernel(const float* __restrict__ x,
                            const float* __restrict__ trans,
                            const float* __restrict__ st,
                            const float* __restrict__ et,
                            const int*   __restrict__ y)
{
    if (blockIdx.x < 256) {
        int b    = blockIdx.x * 8 + (threadIdx.x >> 5);
        int lane = threadIdx.x & 31;
        const int*   yb = y + b * TT;
        const float* xb = x + (size_t)b * TT * LL;
        float num = 0.0f;
        for (int t = lane; t < TT; t += 32) {
            int cur = yb[t];
            num += xb[t * LL + cur];
            if (t + 1 < TT) num += trans[cur * LL + yb[t + 1]];
        }
        #pragma unroll
        for (int o = 16; o > 0; o >>= 1)
            num += __shfl_xor_sync(0xffffffffu, num, o);
        if (lane == 0)
            g_num[b] = num + st[yb[0]] + et[yb[TT - 1]];
    } else {
        int e = (blockIdx.x - 256) * 256 + threadIdx.x;   // 0..16383
        g_E[e] = __expf(trans[e]);
    }
}

// -------------------------------------------------------------------------
// Forward algorithm, linear domain. 148 persistent CTAs x 256 threads.
// CTA owns up to 14 batch rows. Thread (j = tid&127, h = tid>>7):
//   - holds E[i][j] for i in [64h, 64h+64) as 32 f32x2 REGISTERS (no E SMEM)
//   - accumulates partial dot products for ALL 14 rows over its 64 i's
//   - halves exchange partials via SMEM; half h finalizes rows [7h, 7h+7)
// v kept in SMEM; renormalize by row-max every 4 steps (log-scale s[r]).
// -------------------------------------------------------------------------
__global__ void __launch_bounds__(256, 1) crf_fwd_kernel(
    const float* __restrict__ x,
    const float* __restrict__ st,
    const float* __restrict__ et,
    float*       __restrict__ out)
{
    __shared__ float sV[14 * LL];          // current alpha (linear)
    __shared__ u64   sPart[2][7][LL];      // cross-half partial exchange
    __shared__ float sRed[2][7][4];        // per-warp reductions

    const int tid  = threadIdx.x;
    const int j    = tid & 127;
    const int h    = tid >> 7;
    const int win  = (tid >> 5) & 3;       // warp within half

    const int cta   = blockIdx.x;
    const int row0  = (cta * BB) / NCTA;
    const int row1  = ((cta + 1) * BB) / NCTA;
    const int nrows = row1 - row0;         // 13 or 14

    // ---- load E column j, half h into registers, packed by consecutive i ----
    u64 E2[32];
    {
        const float* Eb = g_E + j + (h * 64) * LL;
        #pragma unroll
        for (int k = 0; k < 32; k++)
            E2[k] = pack2(Eb[(2 * k) * LL], Eb[(2 * k + 1) * LL]);
    }
    const float e_end = __expf(et[j]);
    const float stj   = st[j];

    // ---- finalized rows for this half: local rows h*7 + r ----
    const float* xp[7];
    #pragma unroll
    for (int r = 0; r < 7; r++) {
        int g = row0 + h * 7 + r;
        if (g > BB - 1) g = BB - 1;        // pad clamp (results discarded)
        xp[r] = x + (size_t)g * (TT * LL) + j;
    }

    // ---- t = 0 init ----
    #pragma unroll
    for (int r = 0; r < 7; r++)
        sV[(h * 7 + r) * LL + j] = __expf(stj + xp[r][0]);
    float s[7];
    #pragma unroll
    for (int r = 0; r < 7; r++) s[r] = 0.0f;
    __syncthreads();

    for (int t = 1; t < TT; t++) {
        // emissions for the rows this half finalizes (coalesced 512B)
        float xr[7];
        #pragma unroll
        for (int r = 0; r < 7; r++) xr[r] = xp[r][t * LL];

        // partial dot products over this half's 64 i's, all 14 rows
        u64 acc[14];
        #pragma unroll
        for (int q = 0; q < 14; q++) acc[q] = 0ull;

        const char* vb = (const char*)(sV + h * 64);
        #pragma unroll
        for (int ib = 0; ib < 16; ib++) {
            #pragma unroll
            for (int q = 0; q < 14; q++) {
                ulonglong2 vq = *(const ulonglong2*)(vb + q * (LL * 4) + ib * 16);
                acc[q] = ffma2(vq.x, E2[2 * ib],     acc[q]);
                acc[q] = ffma2(vq.y, E2[2 * ib + 1], acc[q]);
            }
        }

        // hand my partials for the OTHER half's rows across
        #pragma unroll
        for (int r = 0; r < 7; r++)
            sPart[h][r][j] = acc[(1 - h) * 7 + r];
        __syncthreads();

        // combine + emission for my rows
        float val[7];
        #pragma unroll
        for (int r = 0; r < 7; r++) {
            u64 tot = fadd2(acc[h * 7 + r], sPart[1 - h][r][j]);
            float lo, hi;
            unpack2(tot, lo, hi);
            val[r] = (lo + hi) * __expf(xr[r]);
        }

        if ((t & 3) == 0) {   // renormalize by row max, track log-scale
            #pragma unroll
            for (int r = 0; r < 7; r++) {
                float m = val[r];
                #pragma unroll
                for (int o = 16; o > 0; o >>= 1)
                    m = fmaxf(m, __shfl_xor_sync(0xffffffffu, m, o));
                if ((tid & 31) == 0) sRed[h][r][win] = m;
            }
            __syncthreads();
            #pragma unroll
            for (int r = 0; r < 7; r++) {
                const float* p = sRed[h][r];
                float m = fmaxf(fmaxf(p[0], p[1]), fmaxf(p[2], p[3]));
                val[r] *= (1.0f / m);
                s[r] += logf(m);
            }
        }

        #pragma unroll
        for (int r = 0; r < 7; r++)
            sV[(h * 7 + r) * LL + j] = val[r];
        __syncthreads();
    }

    // ---- epilogue: Z = sum_j v[j] * exp(end[j]) ----
    #pragma unroll
    for (int r = 0; r < 7; r++) {
        float z = sV[(h * 7 + r) * LL + j] * e_end;
        #pragma unroll
        for (int o = 16; o > 0; o >>= 1)
            z += __shfl_xor_sync(0xffffffffu, z, o);
        if ((tid & 31) == 0) sRed[h][r][win] = z;
    }
    __syncthreads();
    if (j == 0) {
        #pragma unroll
        for (int r = 0; r < 7; r++) {
            int local = h * 7 + r;
            if (local < nrows) {
                const float* p = sRed[h][r];
                float Z = (p[0] + p[1]) + (p[2] + p[3]);
                int g = row0 + local;
                out[g] = g_num[g] - (s[r] + logf(Z));
            }
        }
    }
}

// -------------------------------------------------------------------------
extern "C" void kernel_launch(void* const* d_in, const int* in_sizes, int n_in,
                              void* d_out, int out_size)
{
    const float* x     = (const float*)d_in[0];
    const float* trans = (const float*)d_in[1];
    const float* st    = (const float*)d_in[2];
    const float* et    = (const float*)d_in[3];
    const int*   y     = (const int*)  d_in[4];
    float*       out   = (float*)d_out;

    prep_kernel<<<320, 256>>>(x, trans, st, et, y);
    crf_fwd_kernel<<<NCTA, 256>>>(x, st, et, out);
}

// round 3
// speedup vs baseline: 1.2670x; 1.2373x over previous
#include <cuda_runtime.h>
#include <math.h>

#define BB 2048
#define TT 80
#define LL 128
#define NC 296            // 2 CTAs per SM

typedef unsigned long long u64;

__device__ float g_E[LL * LL];   // exp(trans)
__device__ float g_num[BB];      // gold-path numerator

// ---- packed f32x2 helpers ----
__device__ __forceinline__ u64 ffma2(u64 a, u64 b, u64 c) {
    u64 d;
    asm("fma.rn.f32x2 %0, %1, %2, %3;" : "=l"(d) : "l"(a), "l"(b), "l"(c));
    return d;
}
__device__ __forceinline__ u64 fadd2(u64 a, u64 b) {
    u64 d;
    asm("add.rn.f32x2 %0, %1, %2;" : "=l"(d) : "l"(a), "l"(b));
    return d;
}
__device__ __forceinline__ u64 pack2(float lo, float hi) {
    u64 d;
    asm("mov.b64 %0, {%1, %2};" : "=l"(d)
        : "r"(__float_as_uint(lo)), "r"(__float_as_uint(hi)));
    return d;
}
__device__ __forceinline__ void unpack2(u64 v, float& lo, float& hi) {
    unsigned a, b;
    asm("mov.b64 {%0, %1}, %2;" : "=r"(a), "=r"(b) : "l"(v));
    lo = __uint_as_float(a);
    hi = __uint_as_float(b);
}

// -------------------------------------------------------------------------
__global__ void prep_kernel(const float* __restrict__ x,
                            const float* __restrict__ trans,
                            const float* __restrict__ st,
                            const float* __restrict__ et,
                            const int*   __restrict__ y)
{
    if (blockIdx.x < 256) {
        int b    = blockIdx.x * 8 + (threadIdx.x >> 5);
        int lane = threadIdx.x & 31;
        const int*   yb = y + b * TT;
        const float* xb = x + (size_t)b * TT * LL;
        float num = 0.0f;
        for (int t = lane; t < TT; t += 32) {
            int cur = yb[t];
            num += xb[t * LL + cur];
            if (t + 1 < TT) num += trans[cur * LL + yb[t + 1]];
        }
        #pragma unroll
        for (int o = 16; o > 0; o >>= 1)
            num += __shfl_xor_sync(0xffffffffu, num, o);
        if (lane == 0)
            g_num[b] = num + st[yb[0]] + et[yb[TT - 1]];
    } else {
        int e = (blockIdx.x - 256) * 256 + threadIdx.x;
        g_E[e] = __expf(trans[e]);
    }
}

// -------------------------------------------------------------------------
// Forward algorithm, linear domain. 296 CTAs (2/SM) x 256 threads.
// CTA owns up to 7 batch rows. Thread (j = tid&127, h = tid>>7):
//   - E[i][j] for i in [64h, 64h+64) in registers (32 f32x2)
//   - accumulates partials for all 7 rows over its 64 i's
//   - half 0 finalizes rows 0..3, half 1 finalizes rows 4..6
// -------------------------------------------------------------------------
__global__ void __launch_bounds__(256, 2) crf_fwd_kernel(
    const float* __restrict__ x,
    const float* __restrict__ st,
    const float* __restrict__ et,
    float*       __restrict__ out)
{
    __shared__ float sV[7 * LL];      // current alpha (linear)
    __shared__ u64   sPart[7][LL];    // cross-half partial exchange
    __shared__ float sRed[7][4];      // per-warp reductions

    const int tid = threadIdx.x;
    const int j   = tid & 127;
    const int h   = tid >> 7;
    const int win = (tid >> 5) & 3;

    const int cta   = blockIdx.x;
    const int row0  = (cta * BB) / NC;
    const int nrows = ((cta + 1) * BB) / NC - row0;   // 6 or 7

    const int rb = h * 4;             // finalized local row base
    const int rn = 4 - h;             // 4 rows for h0, 3 for h1

    // E column j, rows [64h, 64h+64), packed by consecutive i
    u64 E2[32];
    {
        const float* Eb = g_E + j + (h * 64) * LL;
        #pragma unroll
        for (int k = 0; k < 32; k++)
            E2[k] = pack2(Eb[(2 * k) * LL], Eb[(2 * k + 1) * LL]);
    }
    const float e_end = __expf(et[j]);

    // pointers for the rows this half finalizes (clamped; padded discarded)
    const float* xq[4];
    #pragma unroll
    for (int r = 0; r < 4; r++) {
        int g = row0 + rb + r;
        if (g > BB - 1) g = BB - 1;
        xq[r] = x + (size_t)g * (TT * LL) + j;
    }

    // t = 0 init
    {
        const float stj = st[j];
        #pragma unroll
        for (int r = 0; r < 4; r++)
            if (r < rn) sV[(rb + r) * LL + j] = __expf(stj + xq[r][0]);
    }
    float s[4] = {0.f, 0.f, 0.f, 0.f};
    __syncthreads();

    for (int t = 1; t < TT; t++) {
        // emissions for my finalized rows
        float xr[4];
        #pragma unroll
        for (int r = 0; r < 4; r++)
            xr[r] = (r < rn) ? xq[r][t * LL] : 0.0f;

        // partial dots over my 64 i's for ALL 7 rows
        u64 acc[7];
        #pragma unroll
        for (int q = 0; q < 7; q++) acc[q] = 0ull;

        const char* vb = (const char*)sV + h * 256;
        #pragma unroll
        for (int ib = 0; ib < 16; ib++) {
            #pragma unroll
            for (int q = 0; q < 7; q++) {
                ulonglong2 vq = *(const ulonglong2*)(vb + q * (LL * 4) + ib * 16);
                acc[q] = ffma2(vq.x, E2[2 * ib],     acc[q]);
                acc[q] = ffma2(vq.y, E2[2 * ib + 1], acc[q]);
            }
        }

        // hand partials for the OTHER half's rows across
        if (h == 0) {
            #pragma unroll
            for (int r = 0; r < 3; r++) sPart[4 + r][j] = acc[4 + r];
        } else {
            #pragma unroll
            for (int r = 0; r < 4; r++) sPart[r][j] = acc[r];
        }
        __syncthreads();

        // combine + emission for my rows
        float val[4];
        #pragma unroll
        for (int r = 0; r < 4; r++) {
            if (r < rn) {
                u64 tot = fadd2(acc[rb + r], sPart[rb + r][j]);
                float lo, hi;
                unpack2(tot, lo, hi);
                val[r] = (lo + hi) * __expf(xr[r]);
            } else val[r] = 1.0f;
        }

        if ((t & 3) == 0) {   // renormalize by row max
            #pragma unroll
            for (int r = 0; r < 4; r++) {
                if (r < rn) {
                    float m = val[r];
                    #pragma unroll
                    for (int o = 16; o > 0; o >>= 1)
                        m = fmaxf(m, __shfl_xor_sync(0xffffffffu, m, o));
                    if ((tid & 31) == 0) sRed[rb + r][win] = m;
                }
            }
            __syncthreads();
            #pragma unroll
            for (int r = 0; r < 4; r++) {
                if (r < rn) {
                    const float* p = sRed[rb + r];
                    float m = fmaxf(fmaxf(p[0], p[1]), fmaxf(p[2], p[3]));
                    val[r] *= (1.0f / m);
                    s[r] += logf(m);
                }
            }
        }

        #pragma unroll
        for (int r = 0; r < 4; r++)
            if (r < rn) sV[(rb + r) * LL + j] = val[r];
        __syncthreads();
    }

    // epilogue: Z = sum_j v[j] * exp(end[j])
    #pragma unroll
    for (int r = 0; r < 4; r++) {
        if (r < rn) {
            float z = sV[(rb + r) * LL + j] * e_end;
            #pragma unroll
            for (int o = 16; o > 0; o >>= 1)
                z += __shfl_xor_sync(0xffffffffu, z, o);
            if ((tid & 31) == 0) sRed[rb + r][win] = z;
        }
    }
    __syncthreads();
    if (j == 0) {
        #pragma unroll
        for (int r = 0; r < 4; r++) {
            int local = rb + r;
            if (r < rn && local < nrows) {
                const float* p = sRed[local];
                float Z = (p[0] + p[1]) + (p[2] + p[3]);
                int g = row0 + local;
                out[g] = g_num[g] - (s[r] + logf(Z));
            }
        }
    }
}

// -------------------------------------------------------------------------
extern "C" void kernel_launch(void* const* d_in, const int* in_sizes, int n_in,
                              void* d_out, int out_size)
{
    const float* x     = (const float*)d_in[0];
    const float* trans = (const float*)d_in[1];
    const float* st    = (const float*)d_in[2];
    const float* et    = (const float*)d_in[3];
    const int*   y     = (const int*)  d_in[4];
    float*       out   = (float*)d_out;

    prep_kernel<<<320, 256>>>(x, trans, st, et, y);
    crf_fwd_kernel<<<NC, 256>>>(x, st, et, out);
}

// round 4
// speedup vs baseline: 1.3613x; 1.0745x over previous
#include <cuda_runtime.h>
#include <math.h>

#define BB 2048
#define TT 80
#define LL 128
#define NC 296            // 2 CTAs per SM

typedef unsigned long long u64;

__device__ float g_E[LL * LL];   // exp(trans)
__device__ float g_num[BB];      // gold-path numerator

// ---- packed f32x2 helpers (FFMA2 is PTX-only) ----
__device__ __forceinline__ u64 ffma2(u64 a, u64 b, u64 c) {
    u64 d;
    asm("fma.rn.f32x2 %0, %1, %2, %3;" : "=l"(d) : "l"(a), "l"(b), "l"(c));
    return d;
}
__device__ __forceinline__ u64 pack2(float lo, float hi) {
    u64 d;
    asm("mov.b64 %0, {%1, %2};" : "=l"(d)
        : "r"(__float_as_uint(lo)), "r"(__float_as_uint(hi)));
    return d;
}
__device__ __forceinline__ void unpack2(u64 v, float& lo, float& hi) {
    unsigned a, b;
    asm("mov.b64 {%0, %1}, %2;" : "=r"(a), "=r"(b) : "l"(v));
    lo = __uint_as_float(a);
    hi = __uint_as_float(b);
}

// -------------------------------------------------------------------------
__global__ void prep_kernel(const float* __restrict__ x,
                            const float* __restrict__ trans,
                            const float* __restrict__ st,
                            const float* __restrict__ et,
                            const int*   __restrict__ y)
{
    if (blockIdx.x < 256) {
        int b    = blockIdx.x * 8 + (threadIdx.x >> 5);
        int lane = threadIdx.x & 31;
        const int*   yb = y + b * TT;
        const float* xb = x + (size_t)b * TT * LL;
        float num = 0.0f;
        for (int t = lane; t < TT; t += 32) {
            int cur = yb[t];
            num += xb[t * LL + cur];
            if (t + 1 < TT) num += trans[cur * LL + yb[t + 1]];
        }
        #pragma unroll
        for (int o = 16; o > 0; o >>= 1)
            num += __shfl_xor_sync(0xffffffffu, num, o);
        if (lane == 0)
            g_num[b] = num + st[yb[0]] + et[yb[TT - 1]];
    } else {
        int e = (blockIdx.x - 256) * 256 + threadIdx.x;
        g_E[e] = __expf(trans[e]);
    }
}

// -------------------------------------------------------------------------
// Forward recursion, linear domain. 296 CTAs (2/SM) x 256 threads, 7 rows/CTA.
// Lane (q = lane>>3, jj8 = lane&7); jj = warp*8+jj8; thread owns columns
// j0=2*jj, j0+1 and i-slice [32q, 32q+32). E[i][j] pre-rotated in 32 f32x2
// registers. Inner: per row, 8 LDS.128 (4 distinct chunks per wavefront via
// q-rotation -> conflict-free, 64B useful) + 32 FFMA2. i-reduction by
// shfl.bfly(8,16). Double-buffered sV -> ONE __syncthreads per step.
// -------------------------------------------------------------------------
__global__ void __launch_bounds__(256, 2) crf_fwd_kernel(
    const float* __restrict__ x,
    const float* __restrict__ st,
    const float* __restrict__ et,
    float*       __restrict__ out)
{
    __shared__ float sV[2][7][LL];    // double-buffered alpha (linear)
    __shared__ float sRed[7][8];      // cross-warp reductions

    const int tid  = threadIdx.x;
    const int lane = tid & 31;
    const int w    = tid >> 5;
    const int q    = lane >> 3;
    const int jj   = w * 8 + (lane & 7);
    const int j0   = 2 * jj;

    const int cta   = blockIdx.x;
    const int row0  = (cta * BB) / NC;
    const int nrows = ((cta + 1) * BB) / NC - row0;   // 6 or 7

    // E registers, pre-rotated: chunk order for this thread is c=(m+q)&7.
    // E2[m*4 + p*2 + js] = (E[i][j0+js], E[i+1][j0+js]) with i = 32q+4c+2p.
    u64 E2[32];
    #pragma unroll
    for (int m = 0; m < 8; m++) {
        int i0 = 32 * q + 4 * ((m + q) & 7);
        #pragma unroll
        for (int p = 0; p < 2; p++) {
            int i = i0 + 2 * p;
            #pragma unroll
            for (int js = 0; js < 2; js++)
                E2[m * 4 + p * 2 + js] =
                    pack2(g_E[i * LL + j0 + js], g_E[(i + 1) * LL + j0 + js]);
        }
    }

    const float ee0 = __expf(et[j0]);
    const float ee1 = __expf(et[j0 + 1]);

    // x base for this thread's column pair; rows are consecutive.
    const float* xb = x + (size_t)row0 * (TT * LL) + j0;

    // ---- t = 0 init (writer: q == r&3) ----
    {
        float s0 = st[j0], s1 = st[j0 + 1];
        #pragma unroll
        for (int r = 0; r < 7; r++) {
            if (q == (r & 3)) {
                float v0 = __expf(s0 + xb[r * (TT * LL)]);
                float v1 = __expf(s1 + xb[r * (TT * LL) + 1]);
                *(u64*)&sV[0][r][j0] = pack2(v0, v1);
            }
        }
    }
    float s[7];
    #pragma unroll
    for (int r = 0; r < 7; r++) s[r] = 0.0f;
    __syncthreads();

    for (int t = 1; t < TT; t++) {
        const int cur = (t - 1) & 1;
        const int nxt = t & 1;

        // prefetch emissions (hidden under the FMA loop)
        u64 xr[7];
        #pragma unroll
        for (int r = 0; r < 7; r++)
            xr[r] = *(const u64*)(xb + r * (TT * LL) + t * LL);

        const char* vbase = (const char*)&sV[cur][0][0];
        float val[7][2];

        // ---- row group 1: rows 0..3 ----
        {
            u64 acc[4][2];
            #pragma unroll
            for (int r = 0; r < 4; r++) { acc[r][0] = 0ull; acc[r][1] = 0ull; }
            #pragma unroll
            for (int m = 0; m < 8; m++) {
                const int off = q * 128 + ((m + q) & 7) * 16;   // bytes
                #pragma unroll
                for (int r = 0; r < 4; r++) {
                    ulonglong2 vv = *(const ulonglong2*)(vbase + r * 512 + off);
                    acc[r][0] = ffma2(vv.x, E2[m * 4 + 0], acc[r][0]);
                    acc[r][1] = ffma2(vv.x, E2[m * 4 + 1], acc[r][1]);
                    acc[r][0] = ffma2(vv.y, E2[m * 4 + 2], acc[r][0]);
                    acc[r][1] = ffma2(vv.y, E2[m * 4 + 3], acc[r][1]);
                }
            }
            #pragma unroll
            for (int r = 0; r < 4; r++) {
                #pragma unroll
                for (int js = 0; js < 2; js++) {
                    float lo, hi;
                    unpack2(acc[r][js], lo, hi);
                    float v = lo + hi;
                    v += __shfl_xor_sync(0xffffffffu, v, 8);
                    v += __shfl_xor_sync(0xffffffffu, v, 16);
                    val[r][js] = v;
                }
            }
        }
        // ---- row group 2: rows 4..6 ----
        {
            u64 acc[3][2];
            #pragma unroll
            for (int r = 0; r < 3; r++) { acc[r][0] = 0ull; acc[r][1] = 0ull; }
            #pragma unroll
            for (int m = 0; m < 8; m++) {
                const int off = q * 128 + ((m + q) & 7) * 16;
                #pragma unroll
                for (int r = 0; r < 3; r++) {
                    ulonglong2 vv = *(const ulonglong2*)(vbase + (4 + r) * 512 + off);
                    acc[r][0] = ffma2(vv.x, E2[m * 4 + 0], acc[r][0]);
                    acc[r][1] = ffma2(vv.x, E2[m * 4 + 1], acc[r][1]);
                    acc[r][0] = ffma2(vv.y, E2[m * 4 + 2], acc[r][0]);
                    acc[r][1] = ffma2(vv.y, E2[m * 4 + 3], acc[r][1]);
                }
            }
            #pragma unroll
            for (int r = 0; r < 3; r++) {
                #pragma unroll
                for (int js = 0; js < 2; js++) {
                    float lo, hi;
                    unpack2(acc[r][js], lo, hi);
                    float v = lo + hi;
                    v += __shfl_xor_sync(0xffffffffu, v, 8);
                    v += __shfl_xor_sync(0xffffffffu, v, 16);
                    val[4 + r][js] = v;
                }
            }
        }

        // ---- emissions ----
        #pragma unroll
        for (int r = 0; r < 7; r++) {
            float xlo, xhi;
            unpack2(xr[r], xlo, xhi);
            val[r][0] *= __expf(xlo);
            val[r][1] *= __expf(xhi);
        }

        // ---- renormalize every 4 steps ----
        if ((t & 3) == 0) {
            #pragma unroll
            for (int r = 0; r < 7; r++) {
                float m2 = fmaxf(val[r][0], val[r][1]);
                #pragma unroll
                for (int o = 16; o > 0; o >>= 1)
                    m2 = fmaxf(m2, __shfl_xor_sync(0xffffffffu, m2, o));
                if (lane == 0) sRed[r][w] = m2;
            }
            __syncthreads();
            #pragma unroll
            for (int r = 0; r < 7; r++) {
                const float* p = sRed[r];
                float m2 = fmaxf(fmaxf(fmaxf(p[0], p[1]), fmaxf(p[2], p[3])),
                                 fmaxf(fmaxf(p[4], p[5]), fmaxf(p[6], p[7])));
                float inv = 1.0f / m2;
                val[r][0] *= inv;
                val[r][1] *= inv;
                s[r] += logf(m2);
            }
        }

        // ---- store next buffer (one writer per (row, column pair)) ----
        #pragma unroll
        for (int r = 0; r < 7; r++) {
            if (q == (r & 3))
                *(u64*)&sV[nxt][r][j0] = pack2(val[r][0], val[r][1]);
        }
        __syncthreads();
    }

    // ---- epilogue: Z = sum_j v[j]*exp(end[j]) ----
    const int lastb = (TT - 1) & 1;
    #pragma unroll
    for (int r = 0; r < 7; r++) {
        float v0, v1;
        unpack2(*(const u64*)&sV[lastb][r][j0], v0, v1);
        float z = v0 * ee0 + v1 * ee1;
        z += __shfl_xor_sync(0xffffffffu, z, 1);
        z += __shfl_xor_sync(0xffffffffu, z, 2);
        z += __shfl_xor_sync(0xffffffffu, z, 4);
        if (lane == 0) sRed[r][w] = z;
    }
    __syncthreads();
    #pragma unroll
    for (int r = 0; r < 7; r++) {
        if (w == r && lane == 0 && r < nrows) {
            const float* p = sRed[r];
            float Z = ((p[0] + p[1]) + (p[2] + p[3])) +
                      ((p[4] + p[5]) + (p[6] + p[7]));
            int g = row0 + r;
            out[g] = g_num[g] - (s[r] + logf(Z));
        }
    }
}

// -------------------------------------------------------------------------
extern "C" void kernel_launch(void* const* d_in, const int* in_sizes, int n_in,
                              void* d_out, int out_size)
{
    const float* x     = (const float*)d_in[0];
    const float* trans = (const float*)d_in[1];
    const float* st    = (const float*)d_in[2];
    const float* et    = (const float*)d_in[3];
    const int*   y     = (const int*)  d_in[4];
    float*       out   = (float*)d_out;

    prep_kernel<<<320, 256>>>(x, trans, st, et, y);
    crf_fwd_kernel<<<NC, 256>>>(x, st, et, out);
}

// round 6
// speedup vs baseline: 2.7682x; 2.0335x over previous
#include <cuda_runtime.h>
#include <cuda_bf16.h>
#include <math.h>
#include <stdint.h>

#define BB 2048
#define TT 80
#define LL 128
#define MT 32             // batch rows per fwd CTA
#define NCF 64            // fwd grid
#define SVS 136           // padded row stride in bf16 elements (272B -> bank shift 4)

__device__ float g_num[BB];                         // gold-path numerator
__device__ uint4 g_P4[(size_t)BB * TT * (LL / 8)];  // exp(x) in bf16, 8 vals per uint4

// ---- helpers ----
__device__ __forceinline__ uint32_t packbf2(float lo, float hi) {
    uint32_t r;
    asm("cvt.rn.satfinite.bf16x2.f32 %0, %1, %2;" : "=r"(r) : "f"(hi), "f"(lo));
    return r;
}
__device__ __forceinline__ float bf_lo(uint32_t w) { return __uint_as_float(w << 16); }
__device__ __forceinline__ float bf_hi(uint32_t w) { return __uint_as_float(w & 0xFFFF0000u); }

__device__ __forceinline__ uint32_t smem_u32(const void* p) {
    uint32_t a;
    asm("{ .reg .u64 t; cvta.to.shared.u64 t, %1; cvt.u32.u64 %0, t; }" : "=r"(a) : "l"(p));
    return a;
}
__device__ __forceinline__ void ldsm4(uint32_t r[4], uint32_t addr) {
    asm volatile("ldmatrix.sync.aligned.m8n8.x4.shared.b16 {%0,%1,%2,%3}, [%4];"
        : "=r"(r[0]), "=r"(r[1]), "=r"(r[2]), "=r"(r[3]) : "r"(addr));
}
__device__ __forceinline__ void mma16816(float d[4], const uint32_t a[4], const uint32_t b[2]) {
    asm volatile("mma.sync.aligned.m16n8k16.row.col.f32.bf16.bf16.f32 "
        "{%0,%1,%2,%3}, {%4,%5,%6,%7}, {%8,%9}, {%0,%1,%2,%3};"
        : "+f"(d[0]), "+f"(d[1]), "+f"(d[2]), "+f"(d[3])
        : "r"(a[0]), "r"(a[1]), "r"(a[2]), "r"(a[3]), "r"(b[0]), "r"(b[1]));
}

// -------------------------------------------------------------------------
// numerators: 256 blocks x 256 thr, one warp per batch row
// -------------------------------------------------------------------------
__global__ void prep_kernel(const float* __restrict__ x,
                            const float* __restrict__ trans,
                            const float* __restrict__ st,
                            const float* __restrict__ et,
                            const int*   __restrict__ y)
{
    int b    = blockIdx.x * 8 + (threadIdx.x >> 5);
    int lane = threadIdx.x & 31;
    const int*   yb = y + b * TT;
    const float* xb = x + (size_t)b * TT * LL;
    float num = 0.0f;
    for (int t = lane; t < TT; t += 32) {
        int cur = yb[t];
        num += xb[t * LL + cur];
        if (t + 1 < TT) num += trans[cur * LL + yb[t + 1]];
    }
    #pragma unroll
    for (int o = 16; o > 0; o >>= 1)
        num += __shfl_xor_sync(0xffffffffu, num, o);
    if (lane == 0)
        g_num[b] = num + st[yb[0]] + et[yb[TT - 1]];
}

// -------------------------------------------------------------------------
// P = exp(x) bf16, flat [b][t][j]. thread = 8 consecutive j.
// -------------------------------------------------------------------------
__global__ void prep_p_kernel(const float* __restrict__ x)
{
    size_t uid = (size_t)blockIdx.x * 256 + threadIdx.x;
    const float4* xs = (const float4*)(x + uid * 8);
    float4 a = xs[0], b = xs[1];
    uint4 o;
    o.x = packbf2(__expf(a.x), __expf(a.y));
    o.y = packbf2(__expf(a.z), __expf(a.w));
    o.z = packbf2(__expf(b.x), __expf(b.y));
    o.w = packbf2(__expf(b.z), __expf(b.w));
    g_P4[uid] = o;
}

// -------------------------------------------------------------------------
// Forward recursion with mma.sync (bf16 HMMA). 64 CTAs x 256 thr (8 warps).
// Warp w owns output n-slice [16w,16w+16). B = E in regs (static).
// A = V via ldmatrix from padded SMEM; P via ldmatrix (D-layout match).
// Double-buffered sV/sP -> 1 sync/step. Per-row renorm every 4 steps.
// -------------------------------------------------------------------------
__global__ void __launch_bounds__(256, 1) crf_fwd_kernel(
    const float* __restrict__ trans,
    const float* __restrict__ st,
    const float* __restrict__ et,
    float*       __restrict__ out)
{
    __shared__ __align__(16) __nv_bfloat16 sV[2][MT * SVS];
    __shared__ __align__(16) __nv_bfloat16 sP[2][MT * SVS];
    __shared__ float sEst[LL];
    __shared__ float sMaxW[8][MT];
    __shared__ float sS[MT];

    const int tid  = threadIdx.x;
    const int w    = tid >> 5;
    const int lane = tid & 31;
    const int gb   = blockIdx.x * MT;

    // ---- static B fragments: Bf[kstep][ntile] = E[k][n] in mma col-B layout ----
    uint32_t Bf[8][2][2];
    {
        const int jn = 16 * w + (lane >> 2);
        const int kb = (lane & 3) * 2;
        #pragma unroll
        for (int ks = 0; ks < 8; ks++)
            #pragma unroll
            for (int nt = 0; nt < 2; nt++) {
                int j  = jn + nt * 8;
                int k0 = ks * 16 + kb;
                Bf[ks][nt][0] = packbf2(__expf(trans[k0 * LL + j]),
                                        __expf(trans[(k0 + 1) * LL + j]));
                Bf[ks][nt][1] = packbf2(__expf(trans[(k0 + 8) * LL + j]),
                                        __expf(trans[(k0 + 9) * LL + j]));
            }
    }
    float eet[2][2];
    {
        int c = 16 * w + (lane & 3) * 2;
        eet[0][0] = __expf(et[c]);     eet[0][1] = __expf(et[c + 1]);
        eet[1][0] = __expf(et[c + 8]); eet[1][1] = __expf(et[c + 9]);
    }
    if (tid < LL) sEst[tid] = __expf(st[tid]);
    if (tid < MT) sS[tid] = 0.0f;

    // ---- P staging ids: thread -> (row, 32B chunk) ----
    const int prow = tid >> 3, ppart = tid & 7;
    const size_t pb0 = (size_t)(gb + prow) * TT * 16 + ppart * 2;

    // stage P0
    {
        uint4 a = g_P4[pb0], b = g_P4[pb0 + 1];
        char* d = (char*)&sP[0][prow * SVS] + ppart * 32;
        *(uint4*)d = a; *(uint4*)(d + 16) = b;
    }
    __syncthreads();
    // V0 = P0 * exp(st)
    #pragma unroll
    for (int c = 0; c < 16; c++) {
        int col = ppart * 16 + c;
        float v = __bfloat162float(sP[0][prow * SVS + col]) * sEst[col];
        sV[0][prow * SVS + col] = __float2bfloat16(v);
    }
    // stage P1
    {
        uint4 a = g_P4[pb0 + 16], b = g_P4[pb0 + 17];
        char* d = (char*)&sP[1][prow * SVS] + ppart * 32;
        *(uint4*)d = a; *(uint4*)(d + 16) = b;
    }

    // ---- ldmatrix / STS per-lane offsets (bytes) ----
    const int rowL = lane & 15;
    const int sel8 = (lane >> 4) * 8;
    uint32_t Aoff[2], Poff[2];
    #pragma unroll
    for (int mt = 0; mt < 2; mt++) {
        Aoff[mt] = ((mt * 16 + rowL) * SVS + sel8) * 2;
        Poff[mt] = ((mt * 16 + rowL) * SVS + 16 * w + sel8) * 2;
    }
    const int rQ = lane >> 2, cQ = (lane & 3) * 2;
    uint32_t Voff[2][2];   // [mt][h]
    #pragma unroll
    for (int mt = 0; mt < 2; mt++)
        #pragma unroll
        for (int h = 0; h < 2; h++)
            Voff[mt][h] = ((mt * 16 + h * 8 + rQ) * SVS + 16 * w + cQ) * 2;

    const uint32_t svb[2] = { smem_u32(&sV[0][0]), smem_u32(&sV[1][0]) };
    const uint32_t spb[2] = { smem_u32(&sP[0][0]), smem_u32(&sP[1][0]) };

    float val[2][2][4];    // [mt][nt][{h0:c,c+1, h1:c,c+1}]

    for (int t = 1; t < TT; t++) {
        const int rd = (t - 1) & 1, wr = t & 1;
        __syncthreads();

        // P_t fragments (D layout)
        uint32_t Pf[2][4];
        ldsm4(Pf[0], spb[wr] + Poff[0]);
        ldsm4(Pf[1], spb[wr] + Poff[1]);

        // prefetch P_{t+1}
        uint4 pra, prb;
        if (t < TT - 1) {
            pra = g_P4[pb0 + (size_t)(t + 1) * 16];
            prb = g_P4[pb0 + (size_t)(t + 1) * 16 + 1];
        }

        // GEMM + emission
        #pragma unroll
        for (int mt = 0; mt < 2; mt++) {
            uint32_t Af[8][4];
            #pragma unroll
            for (int ks = 0; ks < 8; ks++)
                ldsm4(Af[ks], svb[rd] + Aoff[mt] + ks * 32);
            float D[2][4] = {{0.f,0.f,0.f,0.f},{0.f,0.f,0.f,0.f}};
            #pragma unroll
            for (int ks = 0; ks < 8; ks++) {
                mma16816(D[0], Af[ks], Bf[ks][0]);
                mma16816(D[1], Af[ks], Bf[ks][1]);
            }
            #pragma unroll
            for (int nt = 0; nt < 2; nt++) {
                val[mt][nt][0] = D[nt][0] * bf_lo(Pf[mt][2 * nt]);
                val[mt][nt][1] = D[nt][1] * bf_hi(Pf[mt][2 * nt]);
                val[mt][nt][2] = D[nt][2] * bf_lo(Pf[mt][2 * nt + 1]);
                val[mt][nt][3] = D[nt][3] * bf_hi(Pf[mt][2 * nt + 1]);
            }
        }

        // per-row renorm every 4 steps
        if ((t & 3) == 0) {
            float mx[2][2];
            #pragma unroll
            for (int mt = 0; mt < 2; mt++)
                #pragma unroll
                for (int h = 0; h < 2; h++) {
                    float m = fmaxf(fmaxf(val[mt][0][2*h], val[mt][0][2*h+1]),
                                    fmaxf(val[mt][1][2*h], val[mt][1][2*h+1]));
                    m = fmaxf(m, __shfl_xor_sync(0xffffffffu, m, 1));
                    m = fmaxf(m, __shfl_xor_sync(0xffffffffu, m, 2));
                    mx[mt][h] = m;
                }
            if ((lane & 3) == 0) {
                #pragma unroll
                for (int mt = 0; mt < 2; mt++)
                    #pragma unroll
                    for (int h = 0; h < 2; h++)
                        sMaxW[w][mt * 16 + h * 8 + rQ] = mx[mt][h];
            }
            __syncthreads();
            #pragma unroll
            for (int mt = 0; mt < 2; mt++)
                #pragma unroll
                for (int h = 0; h < 2; h++) {
                    int row = mt * 16 + h * 8 + rQ;
                    float m = sMaxW[0][row];
                    #pragma unroll
                    for (int w2 = 1; w2 < 8; w2++) m = fmaxf(m, sMaxW[w2][row]);
                    float inv = 1.0f / m;
                    val[mt][0][2*h] *= inv; val[mt][0][2*h+1] *= inv;
                    val[mt][1][2*h] *= inv; val[mt][1][2*h+1] *= inv;
                    if (w == 0 && (lane & 3) == 0) sS[row] += logf(m);
                }
        }

        if (t < TT - 1) {
            // store new V (bf16 pairs) and P_{t+1}
            char* vb = (char*)&sV[wr][0];
            #pragma unroll
            for (int mt = 0; mt < 2; mt++)
                #pragma unroll
                for (int nt = 0; nt < 2; nt++) {
                    *(uint32_t*)(vb + Voff[mt][0] + nt * 16) =
                        packbf2(val[mt][nt][0], val[mt][nt][1]);
                    *(uint32_t*)(vb + Voff[mt][1] + nt * 16) =
                        packbf2(val[mt][nt][2], val[mt][nt][3]);
                }
            char* pd = (char*)&sP[(t + 1) & 1][prow * SVS] + ppart * 32;
            *(uint4*)pd = pra; *(uint4*)(pd + 16) = prb;
        }
    }

    // ---- epilogue: Z per row ----
    #pragma unroll
    for (int mt = 0; mt < 2; mt++)
        #pragma unroll
        for (int h = 0; h < 2; h++) {
            float z = val[mt][0][2*h] * eet[0][0] + val[mt][0][2*h+1] * eet[0][1]
                    + val[mt][1][2*h] * eet[1][0] + val[mt][1][2*h+1] * eet[1][1];
            z += __shfl_xor_sync(0xffffffffu, z, 1);
            z += __shfl_xor_sync(0xffffffffu, z, 2);
            if ((lane & 3) == 0) sMaxW[w][mt * 16 + h * 8 + rQ] = z;
        }
    __syncthreads();
    if (tid < MT) {
        float Z = 0.0f;
        #pragma unroll
        for (int w2 = 0; w2 < 8; w2++) Z += sMaxW[w2][tid];
        out[gb + tid] = g_num[gb + tid] - (sS[tid] + logf(Z));
    }
}

// -------------------------------------------------------------------------
extern "C" void kernel_launch(void* const* d_in, const int* in_sizes, int n_in,
                              void* d_out, int out_size)
{
    const float* x     = (const float*)d_in[0];
    const float* trans = (const float*)d_in[1];
    const float* st    = (const float*)d_in[2];
    const float* et    = (const float*)d_in[3];
    const int*   y     = (const int*)  d_in[4];
    float*       out   = (float*)d_out;

    prep_kernel<<<256, 256>>>(x, trans, st, et, y);
    prep_p_kernel<<<(size_t)BB * TT * (LL / 8) / 256, 256>>>(x);
    crf_fwd_kernel<<<NCF, 256>>>(trans, st, et, out);
}

// round 7
// speedup vs baseline: 3.1797x; 1.1487x over previous
#include <cuda_runtime.h>
#include <cuda_bf16.h>
#include <math.h>
#include <stdint.h>

#define BB 2048
#define TT 80
#define LL 128
#define MT 16             // batch rows per fwd CTA
#define NCF 128           // fwd grid
#define SVS 136           // padded row stride in bf16 elems (272B, 16B-aligned)

__device__ float g_num[BB];                         // gold-path numerator

// ---- helpers ----
__device__ __forceinline__ uint32_t packbf2(float lo, float hi) {
    uint32_t r;
    asm("cvt.rn.satfinite.bf16x2.f32 %0, %1, %2;" : "=r"(r) : "f"(hi), "f"(lo));
    return r;
}
__device__ __forceinline__ float bf_lo(uint32_t w) { return __uint_as_float(w << 16); }
__device__ __forceinline__ float bf_hi(uint32_t w) { return __uint_as_float(w & 0xFFFF0000u); }

__device__ __forceinline__ uint32_t smem_u32(const void* p) {
    uint32_t a;
    asm("{ .reg .u64 t; cvta.to.shared.u64 t, %1; cvt.u32.u64 %0, t; }" : "=r"(a) : "l"(p));
    return a;
}
__device__ __forceinline__ void ldsm4(uint32_t r[4], uint32_t addr) {
    asm volatile("ldmatrix.sync.aligned.m8n8.x4.shared.b16 {%0,%1,%2,%3}, [%4];"
        : "=r"(r[0]), "=r"(r[1]), "=r"(r[2]), "=r"(r[3]) : "r"(addr));
}
__device__ __forceinline__ void mma16816(float d[4], const uint32_t a[4], const uint32_t b[2]) {
    asm volatile("mma.sync.aligned.m16n8k16.row.col.f32.bf16.bf16.f32 "
        "{%0,%1,%2,%3}, {%4,%5,%6,%7}, {%8,%9}, {%0,%1,%2,%3};"
        : "+f"(d[0]), "+f"(d[1]), "+f"(d[2]), "+f"(d[3])
        : "r"(a[0]), "r"(a[1]), "r"(a[2]), "r"(a[3]), "r"(b[0]), "r"(b[1]));
}

// -------------------------------------------------------------------------
// numerators: one warp per batch row
// -------------------------------------------------------------------------
__global__ void prep_kernel(const float* __restrict__ x,
                            const float* __restrict__ trans,
                            const float* __restrict__ st,
                            const float* __restrict__ et,
                            const int*   __restrict__ y)
{
    int b    = blockIdx.x * 8 + (threadIdx.x >> 5);
    int lane = threadIdx.x & 31;
    const int*   yb = y + b * TT;
    const float* xb = x + (size_t)b * TT * LL;
    // preload tags to maximize gather MLP
    int t0 = lane, t1 = lane + 32, t2 = lane + 64;
    int ya = yb[t0];
    int yb1 = (t1 < TT) ? yb[t1] : 0;
    int yc = (t2 < TT) ? yb[t2] : 0;
    int yn0 = (t0 + 1 < TT) ? yb[t0 + 1] : 0;
    int yn1 = (t1 + 1 < TT) ? yb[t1 + 1] : 0;
    int yn2 = (t2 + 1 < TT) ? yb[t2 + 1] : 0;
    float num = xb[t0 * LL + ya];
    if (t0 + 1 < TT) num += trans[ya * LL + yn0];
    if (t1 < TT) {
        num += xb[t1 * LL + yb1];
        if (t1 + 1 < TT) num += trans[yb1 * LL + yn1];
    }
    if (t2 < TT) {
        num += xb[t2 * LL + yc];
        if (t2 + 1 < TT) num += trans[yc * LL + yn2];
    }
    #pragma unroll
    for (int o = 16; o > 0; o >>= 1)
        num += __shfl_xor_sync(0xffffffffu, num, o);
    if (lane == 0)
        g_num[b] = num + st[yb[0]] + et[yb[TT - 1]];
}

// -------------------------------------------------------------------------
// Forward recursion with mma.sync (bf16 HMMA). 128 CTAs x 256 thr (8 warps).
// Warp w owns n-slice [16w,16w+16). B = exp(trans) in regs (loaded once).
// exp(x) FUSED: x prefetched fp32 one step ahead, exp'd at step tail.
// Split-K (2x4 HMMA chains). Double-buffered sV/sP, 1 sync/step.
// -------------------------------------------------------------------------
__global__ void __launch_bounds__(256, 1) crf_fwd_kernel(
    const float* __restrict__ x,
    const float* __restrict__ trans,
    const float* __restrict__ st,
    const float* __restrict__ et,
    float*       __restrict__ out)
{
    __shared__ __align__(16) __nv_bfloat16 sV[2][MT * SVS];
    __shared__ __align__(16) __nv_bfloat16 sP[2][MT * SVS];
    __shared__ float sSt[LL];
    __shared__ float sMaxW[8][MT];
    __shared__ float sS[MT];

    const int tid  = threadIdx.x;
    const int w    = tid >> 5;
    const int lane = tid & 31;
    const int gb   = blockIdx.x * MT;

    // ---- static B fragments: Bf[kstep][ntile] = exp(trans)[k][n], col-B layout ----
    uint32_t Bf[8][2][2];
    {
        const int jn = 16 * w + (lane >> 2);
        const int kb = (lane & 3) * 2;
        #pragma unroll
        for (int ks = 0; ks < 8; ks++)
            #pragma unroll
            for (int nt = 0; nt < 2; nt++) {
                int j  = jn + nt * 8;
                int k0 = ks * 16 + kb;
                Bf[ks][nt][0] = packbf2(__expf(trans[k0 * LL + j]),
                                        __expf(trans[(k0 + 1) * LL + j]));
                Bf[ks][nt][1] = packbf2(__expf(trans[(k0 + 8) * LL + j]),
                                        __expf(trans[(k0 + 9) * LL + j]));
            }
    }
    float eet[2][2];
    {
        int c = 16 * w + (lane & 3) * 2;
        eet[0][0] = __expf(et[c]);     eet[0][1] = __expf(et[c + 1]);
        eet[1][0] = __expf(et[c + 8]); eet[1][1] = __expf(et[c + 9]);
    }
    if (tid < LL) sSt[tid] = st[tid];
    if (tid < MT) sS[tid] = 0.0f;
    __syncthreads();

    // ---- staging mapping: 16 threads per row, 8 cols each ----
    const int prow = tid >> 4;
    const int pc   = (tid & 15) * 8;
    const float* xrow = x + ((size_t)(gb + prow) * TT) * LL + pc;

    // t = 0: V0 = exp(st + x0);  stage P1 = exp(x1)
    {
        float4 a = *(const float4*)(xrow);
        float4 b = *(const float4*)(xrow + 4);
        uint4 v;
        v.x = packbf2(__expf(sSt[pc + 0] + a.x), __expf(sSt[pc + 1] + a.y));
        v.y = packbf2(__expf(sSt[pc + 2] + a.z), __expf(sSt[pc + 3] + a.w));
        v.z = packbf2(__expf(sSt[pc + 4] + b.x), __expf(sSt[pc + 5] + b.y));
        v.w = packbf2(__expf(sSt[pc + 6] + b.z), __expf(sSt[pc + 7] + b.w));
        *(uint4*)&sV[0][prow * SVS + pc] = v;

        float4 c = *(const float4*)(xrow + LL);
        float4 d = *(const float4*)(xrow + LL + 4);
        uint4 p;
        p.x = packbf2(__expf(c.x), __expf(c.y));
        p.y = packbf2(__expf(c.z), __expf(c.w));
        p.z = packbf2(__expf(d.x), __expf(d.y));
        p.w = packbf2(__expf(d.z), __expf(d.w));
        *(uint4*)&sP[1][prow * SVS + pc] = p;
    }

    // ---- per-lane ldmatrix / STS offsets (bytes) ----
    const int rowL = lane & 15;
    const int sel8 = (lane >> 4) * 8;
    const uint32_t Aoff = (rowL * SVS + sel8) * 2;
    const uint32_t Poff = (rowL * SVS + 16 * w + sel8) * 2;
    const int rQ = lane >> 2, cQ = (lane & 3) * 2;
    uint32_t Voff[2];
    #pragma unroll
    for (int h = 0; h < 2; h++)
        Voff[h] = ((h * 8 + rQ) * SVS + 16 * w + cQ) * 2;

    const uint32_t svb[2] = { smem_u32(&sV[0][0]), smem_u32(&sV[1][0]) };
    const uint32_t spb[2] = { smem_u32(&sP[0][0]), smem_u32(&sP[1][0]) };

    float val[2][4];

    for (int t = 1; t < TT; t++) {
        const int rd = (t - 1) & 1, wr = t & 1;
        __syncthreads();

        // prefetch x_{t+1} (fp32, lands during this step)
        float4 xa, xb2;
        if (t < TT - 1) {
            xa  = *(const float4*)(xrow + (size_t)(t + 1) * LL);
            xb2 = *(const float4*)(xrow + (size_t)(t + 1) * LL + 4);
        }

        // P_t fragment (D layout)
        uint32_t Pf[4];
        ldsm4(Pf, spb[wr] + Poff);

        // A fragments + split-K GEMM
        uint32_t Af[8][4];
        #pragma unroll
        for (int ks = 0; ks < 8; ks++)
            ldsm4(Af[ks], svb[rd] + Aoff + ks * 32);

        float D0[2][4] = {{0.f,0.f,0.f,0.f},{0.f,0.f,0.f,0.f}};
        float D1[2][4] = {{0.f,0.f,0.f,0.f},{0.f,0.f,0.f,0.f}};
        #pragma unroll
        for (int ks = 0; ks < 4; ks++) {
            mma16816(D0[0], Af[ks], Bf[ks][0]);
            mma16816(D0[1], Af[ks], Bf[ks][1]);
            mma16816(D1[0], Af[ks + 4], Bf[ks + 4][0]);
            mma16816(D1[1], Af[ks + 4], Bf[ks + 4][1]);
        }

        #pragma unroll
        for (int nt = 0; nt < 2; nt++) {
            val[nt][0] = (D0[nt][0] + D1[nt][0]) * bf_lo(Pf[2 * nt]);
            val[nt][1] = (D0[nt][1] + D1[nt][1]) * bf_hi(Pf[2 * nt]);
            val[nt][2] = (D0[nt][2] + D1[nt][2]) * bf_lo(Pf[2 * nt + 1]);
            val[nt][3] = (D0[nt][3] + D1[nt][3]) * bf_hi(Pf[2 * nt + 1]);
        }

        // per-row renorm every 4 steps
        if ((t & 3) == 0) {
            #pragma unroll
            for (int h = 0; h < 2; h++) {
                float m = fmaxf(fmaxf(val[0][2*h], val[0][2*h+1]),
                                fmaxf(val[1][2*h], val[1][2*h+1]));
                m = fmaxf(m, __shfl_xor_sync(0xffffffffu, m, 1));
                m = fmaxf(m, __shfl_xor_sync(0xffffffffu, m, 2));
                if ((lane & 3) == 0) sMaxW[w][h * 8 + rQ] = m;
            }
            __syncthreads();
            #pragma unroll
            for (int h = 0; h < 2; h++) {
                int row = h * 8 + rQ;
                float m = sMaxW[0][row];
                #pragma unroll
                for (int w2 = 1; w2 < 8; w2++) m = fmaxf(m, sMaxW[w2][row]);
                float inv = 1.0f / m;
                val[0][2*h] *= inv; val[0][2*h+1] *= inv;
                val[1][2*h] *= inv; val[1][2*h+1] *= inv;
                if (w == 0 && (lane & 3) == 0) sS[row] += logf(m);
            }
        }

        if (t < TT - 1) {
            // store new V (bf16 pairs)
            char* vb = (char*)&sV[wr][0];
            #pragma unroll
            for (int h = 0; h < 2; h++) {
                *(uint32_t*)(vb + Voff[h])      = packbf2(val[0][2*h], val[0][2*h+1]);
                *(uint32_t*)(vb + Voff[h] + 16) = packbf2(val[1][2*h], val[1][2*h+1]);
            }
            // exp + stage P_{t+1}
            uint4 p;
            p.x = packbf2(__expf(xa.x),  __expf(xa.y));
            p.y = packbf2(__expf(xa.z),  __expf(xa.w));
            p.z = packbf2(__expf(xb2.x), __expf(xb2.y));
            p.w = packbf2(__expf(xb2.z), __expf(xb2.w));
            *(uint4*)&sP[(t + 1) & 1][prow * SVS + pc] = p;
        }
    }

    // ---- epilogue: Z per row ----
    #pragma unroll
    for (int h = 0; h < 2; h++) {
        float z = val[0][2*h] * eet[0][0] + val[0][2*h+1] * eet[0][1]
                + val[1][2*h] * eet[1][0] + val[1][2*h+1] * eet[1][1];
        z += __shfl_xor_sync(0xffffffffu, z, 1);
        z += __shfl_xor_sync(0xffffffffu, z, 2);
        if ((lane & 3) == 0) sMaxW[w][h * 8 + rQ] = z;
    }
    __syncthreads();
    if (tid < MT) {
        float Z = 0.0f;
        #pragma unroll
        for (int w2 = 0; w2 < 8; w2++) Z += sMaxW[w2][tid];
        out[gb + tid] = g_num[gb + tid] - (sS[tid] + logf(Z));
    }
}

// -------------------------------------------------------------------------
extern "C" void kernel_launch(void* const* d_in, const int* in_sizes, int n_in,
                              void* d_out, int out_size)
{
    const float* x     = (const float*)d_in[0];
    const float* trans = (const float*)d_in[1];
    const float* st    = (const float*)d_in[2];
    const float* et    = (const float*)d_in[3];
    const int*   y     = (const int*)  d_in[4];
    float*       out   = (float*)d_out;

    prep_kernel<<<256, 256>>>(x, trans, st, et, y);
    crf_fwd_kernel<<<NCF, 256>>>(x, trans, st, et, out);
}

// round 8
// speedup vs baseline: 4.2113x; 1.3244x over previous
#include <cuda_runtime.h>
#include <cuda_bf16.h>
#include <math.h>
#include <stdint.h>

#define BB 2048
#define TT 80
#define LL 128
#define MT 16             // batch rows per CTA
#define NCF 128           // grid
#define SVS 136           // padded V row stride in bf16 elems

// ---- helpers ----
__device__ __forceinline__ uint32_t packbf2(float lo, float hi) {
    uint32_t r;
    asm("cvt.rn.satfinite.bf16x2.f32 %0, %1, %2;" : "=r"(r) : "f"(hi), "f"(lo));
    return r;
}
__device__ __forceinline__ uint32_t smem_u32(const void* p) {
    uint32_t a;
    asm("{ .reg .u64 t; cvta.to.shared.u64 t, %1; cvt.u32.u64 %0, t; }" : "=r"(a) : "l"(p));
    return a;
}
__device__ __forceinline__ void ldsm4(uint32_t r[4], uint32_t addr) {
    asm volatile("ldmatrix.sync.aligned.m8n8.x4.shared.b16 {%0,%1,%2,%3}, [%4];"
        : "=r"(r[0]), "=r"(r[1]), "=r"(r[2]), "=r"(r[3]) : "r"(addr));
}
__device__ __forceinline__ void mma16816(float d[4], const uint32_t a[4], const uint32_t b[2]) {
    asm volatile("mma.sync.aligned.m16n8k16.row.col.f32.bf16.bf16.f32 "
        "{%0,%1,%2,%3}, {%4,%5,%6,%7}, {%8,%9}, {%0,%1,%2,%3};"
        : "+f"(d[0]), "+f"(d[1]), "+f"(d[2]), "+f"(d[3])
        : "r"(a[0]), "r"(a[1]), "r"(a[2]), "r"(a[3]), "r"(b[0]), "r"(b[1]));
}

// -------------------------------------------------------------------------
// Single fused kernel. 128 CTAs x 256 thr (8 warps). Warp w owns n-slice
// [16w,16w+16). B = exp(trans) in regs. V via ldmatrix (double-buffered
// SMEM, bf16). Emissions: per-lane direct LDG.64 at fragment coords,
// prefetched 2 steps ahead; exp off the critical path. Renorm every 8.
// Gold-path numerator gathered at kernel start, reduced at the end.
// -------------------------------------------------------------------------
__global__ void __launch_bounds__(256, 1) crf_fwd_kernel(
    const float* __restrict__ x,
    const float* __restrict__ trans,
    const float* __restrict__ st,
    const float* __restrict__ et,
    const int*   __restrict__ y,
    float*       __restrict__ out)
{
    __shared__ __align__(16) __nv_bfloat16 sV[2][MT * SVS];
    __shared__ float sSt[LL];
    __shared__ float sRed[8][MT];
    __shared__ float sS[MT];
    __shared__ float sNum[MT][16];

    const int tid  = threadIdx.x;
    const int w    = tid >> 5;
    const int lane = tid & 31;
    const int gb   = blockIdx.x * MT;

    // ---- static B fragments: exp(trans)[k][n] in mma col-B layout ----
    uint32_t Bf[8][2][2];
    {
        const int jn = 16 * w + (lane >> 2);
        const int kb = (lane & 3) * 2;
        #pragma unroll
        for (int ks = 0; ks < 8; ks++)
            #pragma unroll
            for (int nt = 0; nt < 2; nt++) {
                int j  = jn + nt * 8;
                int k0 = ks * 16 + kb;
                Bf[ks][nt][0] = packbf2(__expf(trans[k0 * LL + j]),
                                        __expf(trans[(k0 + 1) * LL + j]));
                Bf[ks][nt][1] = packbf2(__expf(trans[(k0 + 8) * LL + j]),
                                        __expf(trans[(k0 + 9) * LL + j]));
            }
    }
    const int rQ  = lane >> 2;
    const int cQ2 = (lane & 3) * 2;
    const int c0  = 16 * w + cQ2;
    float eet[2][2];
    eet[0][0] = __expf(et[c0]);     eet[0][1] = __expf(et[c0 + 1]);
    eet[1][0] = __expf(et[c0 + 8]); eet[1][1] = __expf(et[c0 + 9]);
    if (tid < LL) sSt[tid] = st[tid];
    if (tid < MT) sS[tid] = 0.0f;

    // ---- gold-path numerator: 16 threads per row, 5 time-chunks each ----
    {
        const int nrow = tid >> 4, nsub = tid & 15;
        const int*   yr = y + (gb + nrow) * TT;
        const float* xn = x + (size_t)(gb + nrow) * TT * LL;
        float nacc = 0.0f;
        #pragma unroll
        for (int k = 0; k < 5; k++) {
            int t = nsub + 16 * k;
            int cur = yr[t];
            nacc += xn[t * LL + cur];
            if (t < TT - 1) nacc += trans[cur * LL + yr[t + 1]];
        }
        if (nsub == 0)  nacc += st[yr[0]];
        if (nsub == 15) nacc += et[yr[TT - 1]];
        sNum[nrow][nsub] = nacc;
    }
    __syncthreads();

    // ---- t = 0 init: V0 = exp(st + x0), staged 16 thr/row x 8 cols ----
    {
        const int prow = tid >> 4;
        const int pc   = (tid & 15) * 8;
        const float* xr = x + ((size_t)(gb + prow) * TT) * LL + pc;
        float4 a = *(const float4*)(xr);
        float4 b = *(const float4*)(xr + 4);
        uint4 v;
        v.x = packbf2(__expf(sSt[pc + 0] + a.x), __expf(sSt[pc + 1] + a.y));
        v.y = packbf2(__expf(sSt[pc + 2] + a.z), __expf(sSt[pc + 3] + a.w));
        v.z = packbf2(__expf(sSt[pc + 4] + b.x), __expf(sSt[pc + 5] + b.y));
        v.w = packbf2(__expf(sSt[pc + 6] + b.z), __expf(sSt[pc + 7] + b.w));
        *(uint4*)&sV[0][prow * SVS + pc] = v;
    }

    // ---- emission prefetch pointers (fragment coords) ----
    const float* xrA = x + ((size_t)(gb + rQ)     * TT) * LL + c0;
    const float* xrB = x + ((size_t)(gb + rQ + 8) * TT) * LL + c0;
    float2 xpf[2][4];   // [t&1][h*2+nt]
    #pragma unroll
    for (int nt = 0; nt < 2; nt++) {
        xpf[1][0 + nt] = *(const float2*)(xrA + LL + nt * 8);
        xpf[1][2 + nt] = *(const float2*)(xrB + LL + nt * 8);
        xpf[0][0 + nt] = *(const float2*)(xrA + 2 * LL + nt * 8);
        xpf[0][2 + nt] = *(const float2*)(xrB + 2 * LL + nt * 8);
    }

    // ---- per-lane ldmatrix / STS offsets (bytes) ----
    const int rowL = lane & 15;
    const int sel8 = (lane >> 4) * 8;
    const uint32_t Aoff = (rowL * SVS + sel8) * 2;
    uint32_t Voff[2];
    #pragma unroll
    for (int h = 0; h < 2; h++)
        Voff[h] = ((h * 8 + rQ) * SVS + 16 * w + cQ2) * 2;

    const uint32_t svb[2] = { smem_u32(&sV[0][0]), smem_u32(&sV[1][0]) };

    float val[2][4];

    for (int t = 1; t < TT; t++) {
        const int rd = (t - 1) & 1, wr = t & 1;
        const int b  = t & 1;
        __syncthreads();

        // A fragments
        uint32_t Af[8][4];
        #pragma unroll
        for (int ks = 0; ks < 8; ks++)
            ldsm4(Af[ks], svb[rd] + Aoff + ks * 32);

        // emissions for this step from prefetch buffer
        float P[2][4];
        #pragma unroll
        for (int h = 0; h < 2; h++)
            #pragma unroll
            for (int nt = 0; nt < 2; nt++) {
                float2 xv = xpf[b][h * 2 + nt];
                P[nt][2 * h]     = __expf(xv.x);
                P[nt][2 * h + 1] = __expf(xv.y);
            }
        // refill buffer for t+2
        if (t + 2 < TT) {
            #pragma unroll
            for (int nt = 0; nt < 2; nt++) {
                xpf[b][0 + nt] = *(const float2*)(xrA + (size_t)(t + 2) * LL + nt * 8);
                xpf[b][2 + nt] = *(const float2*)(xrB + (size_t)(t + 2) * LL + nt * 8);
            }
        }

        // split-K GEMM
        float D0[2][4] = {{0.f,0.f,0.f,0.f},{0.f,0.f,0.f,0.f}};
        float D1[2][4] = {{0.f,0.f,0.f,0.f},{0.f,0.f,0.f,0.f}};
        #pragma unroll
        for (int ks = 0; ks < 4; ks++) {
            mma16816(D0[0], Af[ks],     Bf[ks][0]);
            mma16816(D0[1], Af[ks],     Bf[ks][1]);
            mma16816(D1[0], Af[ks + 4], Bf[ks + 4][0]);
            mma16816(D1[1], Af[ks + 4], Bf[ks + 4][1]);
        }
        #pragma unroll
        for (int nt = 0; nt < 2; nt++)
            #pragma unroll
            for (int k = 0; k < 4; k++)
                val[nt][k] = (D0[nt][k] + D1[nt][k]) * P[nt][k];

        // per-row renorm every 8 steps
        if ((t & 7) == 0) {
            #pragma unroll
            for (int h = 0; h < 2; h++) {
                float m = fmaxf(fmaxf(val[0][2*h], val[0][2*h+1]),
                                fmaxf(val[1][2*h], val[1][2*h+1]));
                m = fmaxf(m, __shfl_xor_sync(0xffffffffu, m, 1));
                m = fmaxf(m, __shfl_xor_sync(0xffffffffu, m, 2));
                if ((lane & 3) == 0) sRed[w][h * 8 + rQ] = m;
            }
            __syncthreads();
            #pragma unroll
            for (int h = 0; h < 2; h++) {
                int row = h * 8 + rQ;
                float m = sRed[0][row];
                #pragma unroll
                for (int w2 = 1; w2 < 8; w2++) m = fmaxf(m, sRed[w2][row]);
                float inv = 1.0f / m;
                val[0][2*h] *= inv; val[0][2*h+1] *= inv;
                val[1][2*h] *= inv; val[1][2*h+1] *= inv;
                if (w == 0 && (lane & 3) == 0) sS[row] += logf(m);
            }
        }

        if (t < TT - 1) {
            char* vb = (char*)&sV[wr][0];
            #pragma unroll
            for (int h = 0; h < 2; h++) {
                *(uint32_t*)(vb + Voff[h])      = packbf2(val[0][2*h], val[0][2*h+1]);
                *(uint32_t*)(vb + Voff[h] + 16) = packbf2(val[1][2*h], val[1][2*h+1]);
            }
        }
    }

    // ---- epilogue: Z per row, then out = num - (slog + log Z) ----
    #pragma unroll
    for (int h = 0; h < 2; h++) {
        float z = val[0][2*h] * eet[0][0] + val[0][2*h+1] * eet[0][1]
                + val[1][2*h] * eet[1][0] + val[1][2*h+1] * eet[1][1];
        z += __shfl_xor_sync(0xffffffffu, z, 1);
        z += __shfl_xor_sync(0xffffffffu, z, 2);
        if ((lane & 3) == 0) sRed[w][h * 8 + rQ] = z;
    }
    __syncthreads();
    if (tid < MT) {
        float Z = 0.0f;
        #pragma unroll
        for (int w2 = 0; w2 < 8; w2++) Z += sRed[w2][tid];
        float num = 0.0f;
        #pragma unroll
        for (int k = 0; k < 16; k++) num += sNum[tid][k];
        out[gb + tid] = num - (sS[tid] + logf(Z));
    }
}

// -------------------------------------------------------------------------
extern "C" void kernel_launch(void* const* d_in, const int* in_sizes, int n_in,
                              void* d_out, int out_size)
{
    const float* x     = (const float*)d_in[0];
    const float* trans = (const float*)d_in[1];
    const float* st    = (const float*)d_in[2];
    const float* et    = (const float*)d_in[3];
    const int*   y     = (const int*)  d_in[4];
    float*       out   = (float*)d_out;

    crf_fwd_kernel<<<NCF, 256>>>(x, trans, st, et, y, out);
}